// round 15
// baseline (speedup 1.0000x reference)
#include <cuda_runtime.h>
#include <cuda_fp16.h>
#include <cstdint>

// Problem constants
#define Bc 4
#define Nn 4096
#define Ff 64
#define ISPLIT 128
#define TI 64             // i-rows per block in k_main
#define KSPLIT 2
#define NHC 64            // halves (32 j) per CTA in k_main
#define LOG2E 1.4426950408889634f
#define C08L  (0.8f * LOG2E)
#define SCALE_HS 1024.0f

// ---------------- scratch (device globals; no allocation allowed) ----------
__device__ float  g_h   [Bc * Nn * Ff];
__device__ __half g_p   [(size_t)Bc * Nn * Nn];     // exp weights, fp16 (134MB)
__device__ __half g_hsH [Bc * 128 * 2560];          // packed hs blobs (fp16)
__device__ float  g_fsrc[Bc * Nn];
__device__ float  g_fdst[Bc * Nn];
__device__ float  g_part[ISPLIT][Bc * Nn];
__device__ float  g_pout[KSPLIT][Bc * Nn * Ff];

// ---------------- helpers ---------------------------------------------------
__device__ __forceinline__ float ex2f(float x) {
    float r; asm("ex2.approx.f32 %0, %1;" : "=f"(r) : "f"(x)); return r;
}
__device__ __forceinline__ uint32_t smem_u32(const void* p) {
    uint32_t a;
    asm("{ .reg .u64 t; cvta.to.shared.u64 t, %1; cvt.u32.u64 %0, t; }" : "=r"(a) : "l"(p));
    return a;
}
__device__ __forceinline__ float4 ldcs4(const float* p) {
    float4 v;
    asm("ld.global.cs.v4.f32 {%0,%1,%2,%3}, [%4];"
        : "=f"(v.x), "=f"(v.y), "=f"(v.z), "=f"(v.w) : "l"(p));
    return v;
}
#define CPA16(dst, src) \
    asm volatile("cp.async.cg.shared.global [%0], [%1], 16;" :: "r"(dst), "l"(src))
#define MMA_F16(c, a, b0, b1) \
    asm volatile("mma.sync.aligned.m16n8k16.row.col.f32.f16.f16.f32 " \
        "{%0,%1,%2,%3},{%4,%5,%6,%7},{%8,%9},{%0,%1,%2,%3};" \
        : "+f"((c)[0]), "+f"((c)[1]), "+f"((c)[2]), "+f"((c)[3]) \
        : "r"((a)[0]), "r"((a)[1]), "r"((a)[2]), "r"((a)[3]), "r"(b0), "r"(b1))
#define LDSM_X4(r0, r1, r2, r3, addr) \
    asm volatile("ldmatrix.sync.aligned.m8n8.x4.shared.b16 {%0,%1,%2,%3}, [%4];" \
        : "=r"(r0), "=r"(r1), "=r"(r2), "=r"(r3) : "r"(addr))

// k_main smem: 4 stages of [p tile 64 rows x 80B | hs blob 64 segs x 80B]
#define ST_P    5120u
#define ST_HS   5120u
#define STAGE   (ST_P + ST_HS)       // 10240
#define SM_TOTAL (4u * STAGE)        // 40960 -> 5 CTAs/SM

// ============================================================================
// Kernel 1: h = inp @ W ; fsrc/fdst = 0.2*log2e * (lrelu(h) @ a halves)
// ============================================================================
__global__ __launch_bounds__(256) void k_prep(const float* __restrict__ inp,
                                              const float* __restrict__ W,
                                              const float* __restrict__ a) {
    __shared__ float Ws[64 * 64];
    __shared__ float as[128];
    __shared__ float inps[4][64];
    __shared__ float redS[4][2], redD[4][2];

    const int t = threadIdx.x;
    const int rowBase = blockIdx.x * 4;

    #pragma unroll
    for (int k = 0; k < 16; ++k) Ws[t + k * 256] = W[t + k * 256];
    if (t < 128) as[t] = a[t];

    const int r = t >> 6;
    const int o = t & 63;
    inps[r][o] = inp[(size_t)(rowBase + r) * 64 + o];
    __syncthreads();

    float hv = 0.f;
    #pragma unroll
    for (int f = 0; f < 64; ++f) hv = fmaf(inps[r][f], Ws[f * 64 + o], hv);

    const int gRow = rowBase + r;
    g_h[(size_t)gRow * 64 + o] = hv;

    const float lh = hv > 0.f ? hv : 0.2f * hv;
    float ps = lh * as[o];
    float pd = lh * as[64 + o];
    #pragma unroll
    for (int off = 16; off > 0; off >>= 1) {
        ps += __shfl_xor_sync(0xffffffffu, ps, off);
        pd += __shfl_xor_sync(0xffffffffu, pd, off);
    }
    const int wh = (t >> 5) & 1;
    if ((t & 31) == 0) { redS[r][wh] = ps; redD[r][wh] = pd; }
    __syncthreads();
    if ((t & 63) == 0) {
        g_fsrc[gRow] = 0.2f * LOG2E * (redS[r][0] + redS[r][1]);
        g_fdst[gRow] = 0.2f * LOG2E * (redD[r][0] + redD[r][1]);
    }
}

// ============================================================================
// Kernel 2: k_expsum for ONE j-half — exp ONCE: p = (t>0 ? 2^t : 0) fp16;
// colsum partials. grid (1, 128, Bc) = 512 CTAs, 32 i-rows x 2048 j each.
// adj loads .cs (evict-first) so the freshly written p half persists in L2
// for the following k_main(ks) launch.
// ============================================================================
__global__ __launch_bounds__(256) void k_expsum(const float* __restrict__ adj, int jh) {
    const int b  = blockIdx.z;
    const int j8 = jh * 2048 + (blockIdx.x * 256 + threadIdx.x) * 8;
    const int i0 = blockIdx.y * (Nn / ISPLIT);
    const float4 djA = *(const float4*)(g_fdst + b * Nn + j8);
    const float4 djB = *(const float4*)(g_fdst + b * Nn + j8 + 4);
    const float* __restrict__ fs = g_fsrc + b * Nn + i0;
    const float* __restrict__ ap = adj + ((size_t)b * Nn + i0) * Nn + j8;
    __half* __restrict__ pp = g_p + ((size_t)(b * Nn + i0)) * Nn + j8;

    float4 sA = make_float4(0.f, 0.f, 0.f, 0.f);
    float4 sB = make_float4(0.f, 0.f, 0.f, 0.f);
    #pragma unroll 4
    for (int r = 0; r < Nn / ISPLIT; ++r) {
        const float ci = fs[r];
        const float4 a0 = ldcs4(ap + (size_t)r * Nn);
        const float4 a1 = ldcs4(ap + (size_t)r * Nn + 4);
        float e0 = 0.f, e1 = 0.f, e2 = 0.f, e3 = 0.f;
        float e4 = 0.f, e5 = 0.f, e6 = 0.f, e7 = 0.f;
        {
            const float t0 = fmaf(C08L, a0.x, ci + djA.x);
            const float t1 = fmaf(C08L, a0.y, ci + djA.y);
            const float t2 = fmaf(C08L, a0.z, ci + djA.z);
            const float t3 = fmaf(C08L, a0.w, ci + djA.w);
            const float t4 = fmaf(C08L, a1.x, ci + djB.x);
            const float t5 = fmaf(C08L, a1.y, ci + djB.y);
            const float t6 = fmaf(C08L, a1.z, ci + djB.z);
            const float t7 = fmaf(C08L, a1.w, ci + djB.w);
            if (t0 > 0.f) e0 = ex2f(t0);
            if (t1 > 0.f) e1 = ex2f(t1);
            if (t2 > 0.f) e2 = ex2f(t2);
            if (t3 > 0.f) e3 = ex2f(t3);
            if (t4 > 0.f) e4 = ex2f(t4);
            if (t5 > 0.f) e5 = ex2f(t5);
            if (t6 > 0.f) e6 = ex2f(t6);
            if (t7 > 0.f) e7 = ex2f(t7);
        }
        sA.x += e0; sA.y += e1; sA.z += e2; sA.w += e3;
        sB.x += e4; sB.y += e5; sB.z += e6; sB.w += e7;
        __half2 h0 = __floats2half2_rn(e0, e1);
        __half2 h1 = __floats2half2_rn(e2, e3);
        __half2 h2 = __floats2half2_rn(e4, e5);
        __half2 h3 = __floats2half2_rn(e6, e7);
        uint4 w;
        w.x = *reinterpret_cast<uint32_t*>(&h0);
        w.y = *reinterpret_cast<uint32_t*>(&h1);
        w.z = *reinterpret_cast<uint32_t*>(&h2);
        w.w = *reinterpret_cast<uint32_t*>(&h3);
        *reinterpret_cast<uint4*>(pp + (size_t)r * Nn) = w;
    }
    *(float4*)(&g_part[blockIdx.y][b * Nn + j8])     = sA;
    *(float4*)(&g_part[blockIdx.y][b * Nn + j8 + 4]) = sB;
}

// ============================================================================
// Kernel 3: k_hpack for ONE j-half: reduce 128 partials; pack hs*1024/colsum
// (fp16) into B-frag blobs; degenerate columns patched. grid (32, Bc).
// ============================================================================
__global__ __launch_bounds__(256) void k_hpack(int jh) {
    __shared__ float sc[64];
    __shared__ float qsum[4][64];
    __shared__ int degCnt;
    __shared__ int degList[64];
    const int t = threadIdx.x;
    const int c = jh * 32 + blockIdx.x;
    const int b = blockIdx.y;
    const int j0 = c * 64;

    if (t == 0) degCnt = 0;
    {
        const int jl = t & 63;
        const int sl = t >> 6;
        float cs = 0.f;
        #pragma unroll
        for (int s = 0; s < ISPLIT / 4; ++s)
            cs += g_part[sl * (ISPLIT / 4) + s][b * Nn + j0 + jl];
        qsum[sl][jl] = cs;
    }
    __syncthreads();
    if (t < 64) {
        const float cs = qsum[0][t] + qsum[1][t] + qsum[2][t] + qsum[3][t];
        sc[t] = cs > 0.f ? (SCALE_HS / cs) : (SCALE_HS / (float)Nn);
        if (!(cs > 0.f)) {
            const int k = atomicAdd(&degCnt, 1);
            degList[k] = t;
        }
    }
    __syncthreads();

    // Patch degenerate columns of p (normally degCnt == 0)
    for (int l = 0; l < degCnt; ++l) {
        const int j = j0 + degList[l];
        for (int i = t; i < Nn; i += 256)
            g_p[((size_t)(b * Nn) + i) * Nn + j] = __ushort_as_half(0x3C00);
    }

    __half* __restrict__ dstBase = g_hsH + (size_t)(b * 128 + c * 2) * 2560;
    #pragma unroll
    for (int r = 0; r < 16; ++r) {
        const int o = t + r * 256;              // 0..4095
        const int hh2 = o >> 11;
        const int rem = o & 2047;
        const int seg = rem >> 5, pos = rem & 31;
        const int ks2 = seg >> 5, lane = seg & 31;
        const int lq = lane >> 2, lm = lane & 3;
        const int nt = pos >> 2, q = pos & 3;
        const int jl = hh2 * 32 + ks2 * 16 + 2 * lm + (q & 1) + (q >> 1) * 8;
        const int f  = nt * 8 + lq;
        const float v = g_h[((size_t)(b * Nn) + j0 + jl) * 64 + f] * sc[jl];
        dstBase[(size_t)hh2 * 2560 + seg * 40 + pos] = __float2half_rn(v);
    }
}

// ============================================================================
// Kernel 4 (hot): fp16 GEMM partial for ONE k-half via mma.m16n8k16.
// A fragments via ldmatrix.x4; TI=64, 128 thr = 4 warps x 16 rows; 4-deep
// half pipeline. grid (64, Bc) = 256 CTAs; smem 40KB -> 5 CTAs/SM.
// ============================================================================
__device__ __forceinline__ void issue_half(uint32_t stg,
                                           const __half* __restrict__ pB,
                                           const __half* __restrict__ hsHb,
                                           int hglob, int t) {
    // p tile: 64 rows x 64B data, dst row stride 80B (256 quads)
    const __half* __restrict__ psrc = pB + hglob * 32;
    #pragma unroll
    for (int q = 0; q < 2; ++q) {
        const int quad = t + q * 128;
        const int row = quad >> 2, c4 = quad & 3;
        CPA16(stg + (uint32_t)row * 80u + (uint32_t)c4 * 16u,
              psrc + (size_t)row * Nn + c4 * 8);
    }
    // hs blob: flat 5120B = 320 quads
    const __half* __restrict__ hsrc = hsHb + (size_t)hglob * 2560;
    const uint32_t hb = stg + ST_P;
    CPA16(hb + (uint32_t)t * 16u, hsrc + t * 8);
    CPA16(hb + (uint32_t)(t + 128) * 16u, hsrc + (t + 128) * 8);
    if (t < 64)
        CPA16(hb + (uint32_t)(t + 256) * 16u, hsrc + (t + 256) * 8);
}

__global__ __launch_bounds__(128, 5) void k_main(int ks) {
    extern __shared__ char dsm[];
    const uint32_t sm = smem_u32(dsm);

    const int t    = threadIdx.x;
    const int wid  = t >> 5;      // warp owns rows wid*16 .. wid*16+15
    const int lane = t & 31;
    const int lq   = lane >> 2;
    const int lm   = lane & 3;
    const int b    = blockIdx.y;
    const int i0   = blockIdx.x * TI;
    const int h0   = ks * NHC;

    const __half* __restrict__ pB   = g_p + ((size_t)(b * Nn + i0)) * Nn;
    const __half* __restrict__ hsHb = g_hsH + (size_t)b * 128 * 2560;

    // ldmatrix lane address pieces: tile = lane>>3 (0..3)
    //   row-in-warp-tile = (tile&1)*8 + (lane&7); k-half = tile>>1
    const uint32_t lmRow = (uint32_t)(wid * 16 + ((lane >> 3) & 1) * 8 + (lane & 7));
    const uint32_t lmOff = lmRow * 80u + (uint32_t)(lane >> 4) * 16u;

    float acc[8][4];
    #pragma unroll
    for (int nt = 0; nt < 8; ++nt)
        #pragma unroll
        for (int q = 0; q < 4; ++q) acc[nt][q] = 0.f;

    #pragma unroll
    for (int p = 0; p < 3; ++p) {
        issue_half(sm + (uint32_t)p * STAGE, pB, hsHb, h0 + p, t);
        asm volatile("cp.async.commit_group;" ::: "memory");
    }

    for (int h = 0; h < NHC; ++h) {
        asm volatile("cp.async.wait_group 2;" ::: "memory");
        __syncthreads();
        if (h + 3 < NHC)
            issue_half(sm + (uint32_t)((h + 3) & 3) * STAGE, pB, hsHb,
                       h0 + h + 3, t);
        asm volatile("cp.async.commit_group;" ::: "memory");

        const uint32_t stg = sm + (uint32_t)(h & 3) * STAGE;
        const uint32_t hsb = stg + ST_P;

        #pragma unroll
        for (int ks2 = 0; ks2 < 2; ++ks2) {
            // B fragments: 4 x LDS.128 from seg (ks2*32 + lane)
            uint32_t bfr[16];
            #pragma unroll
            for (int v = 0; v < 4; ++v) {
                const uint32_t ba = hsb + (uint32_t)(ks2 * 32 + lane) * 80u
                                  + (uint32_t)v * 16u;
                asm volatile("ld.shared.v4.b32 {%0,%1,%2,%3}, [%4];"
                             : "=r"(bfr[v * 4]), "=r"(bfr[v * 4 + 1]),
                               "=r"(bfr[v * 4 + 2]), "=r"(bfr[v * 4 + 3])
                             : "r"(ba));
            }
            // A fragment: one ldmatrix.x4 (16 rows x 32B, conflict-free)
            uint32_t au[4];
            LDSM_X4(au[0], au[1], au[2], au[3],
                    stg + lmOff + (uint32_t)(ks2 * 32));
            #pragma unroll
            for (int nt = 0; nt < 8; ++nt) {
                const uint32_t b0 = bfr[(nt >> 1) * 4 + (nt & 1) * 2];
                const uint32_t b1 = bfr[(nt >> 1) * 4 + (nt & 1) * 2 + 1];
                MMA_F16(acc[nt], au, b0, b1);
            }
        }
    }

    // epilogue: undo SCALE_HS; store partials
    float* __restrict__ pout = g_pout[ks] + ((size_t)(b * Nn) + i0 + wid * 16) * 64;
    const float inv = 1.0f / SCALE_HS;
    #pragma unroll
    for (int nt = 0; nt < 8; ++nt) {
        const size_t base = (size_t)lq * 64 + nt * 8 + 2 * lm;
        *(float2*)(pout + base) =
            make_float2(acc[nt][0] * inv, acc[nt][1] * inv);
        *(float2*)(pout + base + 8 * 64) =
            make_float2(acc[nt][2] * inv, acc[nt][3] * inv);
    }
}

// ============================================================================
// Kernel 5: out = relu(p0 + p1)
// ============================================================================
__global__ __launch_bounds__(256) void k_fin(float* __restrict__ out) {
    const int idx = (blockIdx.x * 256 + threadIdx.x) * 4;
    const float4 p0 = *(const float4*)(&g_pout[0][idx]);
    const float4 p1 = *(const float4*)(&g_pout[1][idx]);
    float4 r;
    r.x = fmaxf(p0.x + p1.x, 0.f);
    r.y = fmaxf(p0.y + p1.y, 0.f);
    r.z = fmaxf(p0.z + p1.z, 0.f);
    r.w = fmaxf(p0.w + p1.w, 0.f);
    *(float4*)(out + idx) = r;
}

// ============================================================================
extern "C" void kernel_launch(void* const* d_in, const int* in_sizes, int n_in,
                              void* d_out, int out_size) {
    const float *inp = nullptr, *adj = nullptr, *W = nullptr, *a = nullptr;
    for (int i = 0; i < n_in; ++i) {
        switch (in_sizes[i]) {
            case 1048576:  inp = (const float*)d_in[i]; break; // 4*4096*64
            case 67108864: adj = (const float*)d_in[i]; break; // 4*4096*4096
            case 4096:     W   = (const float*)d_in[i]; break; // 64*64
            case 128:      a   = (const float*)d_in[i]; break; // 128*1
            default: break;
        }
    }
    float* out = (float*)d_out;

    // One-time handle creation — first call is the (uncaptured) correctness
    // run, so no stream/event creation ever happens during graph capture.
    static cudaStream_t s1 = nullptr;
    static cudaEvent_t evP = nullptr, ev0 = nullptr, ev1 = nullptr;
    if (s1 == nullptr) {
        cudaStreamCreateWithFlags(&s1, cudaStreamNonBlocking);
        cudaEventCreateWithFlags(&evP, cudaEventDisableTiming);
        cudaEventCreateWithFlags(&ev0, cudaEventDisableTiming);
        cudaEventCreateWithFlags(&ev1, cudaEventDisableTiming);
        cudaFuncSetAttribute(k_main, cudaFuncAttributeMaxDynamicSharedMemorySize,
                             SM_TOTAL);
    }

    // j-half pipeline: side stream runs the two expsum halves back-to-back;
    // main stream consumes each half as soon as its event fires. main(ks0)
    // overlaps expsum(jh1), reading its p half from L2 (written just before,
    // adj loads are evict-first so the dirty p lines survive).
    k_prep<<<Bc * Nn / 4, 256>>>(inp, W, a);
    cudaEventRecord(evP, 0);
    cudaStreamWaitEvent(s1, evP, 0);

    dim3 gE(1, ISPLIT, Bc);
    k_expsum<<<gE, 256, 0, s1>>>(adj, 0);
    cudaEventRecord(ev0, s1);
    k_expsum<<<gE, 256, 0, s1>>>(adj, 1);
    cudaEventRecord(ev1, s1);

    dim3 gH(32, Bc);
    dim3 gM(64, Bc);
    cudaStreamWaitEvent(0, ev0, 0);
    k_hpack<<<gH, 256>>>(0);
    k_main<<<gM, 128, SM_TOTAL>>>(0);
    cudaStreamWaitEvent(0, ev1, 0);
    k_hpack<<<gH, 256>>>(1);
    k_main<<<gM, 128, SM_TOTAL>>>(1);

    k_fin<<<Bc * Nn * Ff / 1024, 256>>>(out);
}

// round 16
// speedup vs baseline: 1.2584x; 1.2584x over previous
#include <cuda_runtime.h>
#include <cuda_fp16.h>
#include <cstdint>

// Problem constants
#define Bc 4
#define Nn 4096
#define Ff 64
#define ISPLIT 128
#define TI 64             // i-rows per block in k_main
#define KSPLIT 2
#define NHC 64            // halves (32 j) per CTA in k_main
#define LOG2E 1.4426950408889634f
#define C08L  (0.8f * LOG2E)
#define SCALE_HS 1024.0f

// ---------------- scratch (device globals; no allocation allowed) ----------
__device__ float  g_h   [Bc * Nn * Ff];
__device__ __half g_p   [(size_t)Bc * Nn * Nn];     // exp weights, fp16 (134MB)
__device__ __half g_hsH [Bc * 128 * 2560];          // packed hs blobs (fp16)
__device__ float  g_fsrc[Bc * Nn];
__device__ float  g_fdst[Bc * Nn];
__device__ float  g_part[ISPLIT][Bc * Nn];
__device__ __half g_poutH[KSPLIT][Bc * Nn * Ff];    // fp16 k-split partials

// ---------------- helpers ---------------------------------------------------
__device__ __forceinline__ float ex2f(float x) {
    float r; asm("ex2.approx.f32 %0, %1;" : "=f"(r) : "f"(x)); return r;
}
__device__ __forceinline__ uint32_t smem_u32(const void* p) {
    uint32_t a;
    asm("{ .reg .u64 t; cvta.to.shared.u64 t, %1; cvt.u32.u64 %0, t; }" : "=r"(a) : "l"(p));
    return a;
}
__device__ __forceinline__ float4 ldcs4(const float* p) {
    float4 v;
    asm("ld.global.cs.v4.f32 {%0,%1,%2,%3}, [%4];"
        : "=f"(v.x), "=f"(v.y), "=f"(v.z), "=f"(v.w) : "l"(p));
    return v;
}
__device__ __forceinline__ uint32_t packh2(float lo, float hi) {
    __half2 h = __floats2half2_rn(lo, hi);
    return *reinterpret_cast<uint32_t*>(&h);
}
__device__ __forceinline__ float2 h2f2(uint32_t v) {
    __half2 h = *reinterpret_cast<__half2*>(&v);
    return __half22float2(h);
}
#define CPA16(dst, src) \
    asm volatile("cp.async.cg.shared.global [%0], [%1], 16;" :: "r"(dst), "l"(src))
#define MMA_F16(c, a, b0, b1) \
    asm volatile("mma.sync.aligned.m16n8k16.row.col.f32.f16.f16.f32 " \
        "{%0,%1,%2,%3},{%4,%5,%6,%7},{%8,%9},{%0,%1,%2,%3};" \
        : "+f"((c)[0]), "+f"((c)[1]), "+f"((c)[2]), "+f"((c)[3]) \
        : "r"((a)[0]), "r"((a)[1]), "r"((a)[2]), "r"((a)[3]), "r"(b0), "r"(b1))
#define LDSM_X4(r0, r1, r2, r3, addr) \
    asm volatile("ldmatrix.sync.aligned.m8n8.x4.shared.b16 {%0,%1,%2,%3}, [%4];" \
        : "=r"(r0), "=r"(r1), "=r"(r2), "=r"(r3) : "r"(addr))

// k_main smem: 4 stages of [p tile 64 rows x 80B | hs blob 64 segs x 80B]
#define ST_P    5120u
#define ST_HS   5120u
#define STAGE   (ST_P + ST_HS)       // 10240
#define SM_TOTAL (4u * STAGE)        // 40960 -> 5 CTAs/SM

// ============================================================================
// Kernel 1: h = inp @ W ; fsrc/fdst = 0.2*log2e * (lrelu(h) @ a halves)
// ============================================================================
__global__ __launch_bounds__(256) void k_prep(const float* __restrict__ inp,
                                              const float* __restrict__ W,
                                              const float* __restrict__ a) {
    __shared__ float Ws[64 * 64];
    __shared__ float as[128];
    __shared__ float inps[4][64];
    __shared__ float redS[4][2], redD[4][2];

    const int t = threadIdx.x;
    const int rowBase = blockIdx.x * 4;

    #pragma unroll
    for (int k = 0; k < 16; ++k) Ws[t + k * 256] = W[t + k * 256];
    if (t < 128) as[t] = a[t];

    const int r = t >> 6;
    const int o = t & 63;
    inps[r][o] = inp[(size_t)(rowBase + r) * 64 + o];
    __syncthreads();

    float hv = 0.f;
    #pragma unroll
    for (int f = 0; f < 64; ++f) hv = fmaf(inps[r][f], Ws[f * 64 + o], hv);

    const int gRow = rowBase + r;
    g_h[(size_t)gRow * 64 + o] = hv;

    const float lh = hv > 0.f ? hv : 0.2f * hv;
    float ps = lh * as[o];
    float pd = lh * as[64 + o];
    #pragma unroll
    for (int off = 16; off > 0; off >>= 1) {
        ps += __shfl_xor_sync(0xffffffffu, ps, off);
        pd += __shfl_xor_sync(0xffffffffu, pd, off);
    }
    const int wh = (t >> 5) & 1;
    if ((t & 31) == 0) { redS[r][wh] = ps; redD[r][wh] = pd; }
    __syncthreads();
    if ((t & 63) == 0) {
        g_fsrc[gRow] = 0.2f * LOG2E * (redS[r][0] + redS[r][1]);
        g_fdst[gRow] = 0.2f * LOG2E * (redD[r][0] + redD[r][1]);
    }
}

// ============================================================================
// Kernel 2: k_expsum — exp ONCE: p = (t>0 ? 2^t : 0) stored fp16; colsum
// partials accumulated. grid (2, 128, Bc) = 1024 CTAs, 32 rows each.
// ============================================================================
__global__ __launch_bounds__(256) void k_expsum(const float* __restrict__ adj) {
    const int b  = blockIdx.z;
    const int j8 = (blockIdx.x * 256 + threadIdx.x) * 8;
    const int i0 = blockIdx.y * (Nn / ISPLIT);
    const float4 djA = *(const float4*)(g_fdst + b * Nn + j8);
    const float4 djB = *(const float4*)(g_fdst + b * Nn + j8 + 4);
    const float* __restrict__ fs = g_fsrc + b * Nn + i0;
    const float* __restrict__ ap = adj + ((size_t)b * Nn + i0) * Nn + j8;
    __half* __restrict__ pp = g_p + ((size_t)(b * Nn + i0)) * Nn + j8;

    float4 sA = make_float4(0.f, 0.f, 0.f, 0.f);
    float4 sB = make_float4(0.f, 0.f, 0.f, 0.f);
    #pragma unroll 4
    for (int r = 0; r < Nn / ISPLIT; ++r) {
        const float ci = fs[r];
        const float4 a0 = ldcs4(ap + (size_t)r * Nn);
        const float4 a1 = ldcs4(ap + (size_t)r * Nn + 4);
        float e0 = 0.f, e1 = 0.f, e2 = 0.f, e3 = 0.f;
        float e4 = 0.f, e5 = 0.f, e6 = 0.f, e7 = 0.f;
        {
            const float t0 = fmaf(C08L, a0.x, ci + djA.x);
            const float t1 = fmaf(C08L, a0.y, ci + djA.y);
            const float t2 = fmaf(C08L, a0.z, ci + djA.z);
            const float t3 = fmaf(C08L, a0.w, ci + djA.w);
            const float t4 = fmaf(C08L, a1.x, ci + djB.x);
            const float t5 = fmaf(C08L, a1.y, ci + djB.y);
            const float t6 = fmaf(C08L, a1.z, ci + djB.z);
            const float t7 = fmaf(C08L, a1.w, ci + djB.w);
            if (t0 > 0.f) e0 = ex2f(t0);
            if (t1 > 0.f) e1 = ex2f(t1);
            if (t2 > 0.f) e2 = ex2f(t2);
            if (t3 > 0.f) e3 = ex2f(t3);
            if (t4 > 0.f) e4 = ex2f(t4);
            if (t5 > 0.f) e5 = ex2f(t5);
            if (t6 > 0.f) e6 = ex2f(t6);
            if (t7 > 0.f) e7 = ex2f(t7);
        }
        sA.x += e0; sA.y += e1; sA.z += e2; sA.w += e3;
        sB.x += e4; sB.y += e5; sB.z += e6; sB.w += e7;
        uint4 w;
        w.x = packh2(e0, e1);
        w.y = packh2(e2, e3);
        w.z = packh2(e4, e5);
        w.w = packh2(e6, e7);
        *reinterpret_cast<uint4*>(pp + (size_t)r * Nn) = w;
    }
    *(float4*)(&g_part[blockIdx.y][b * Nn + j8])     = sA;
    *(float4*)(&g_part[blockIdx.y][b * Nn + j8 + 4]) = sB;
}

// ============================================================================
// Kernel 3: reduce 128 partials; pack hs*1024/colsum (fp16) into B-frag blobs;
// degenerate columns patched in-place. Half-blob granularity: grid (128, Bc),
// each CTA owns 32 j (one half-blob = 2048 halfs).
// ============================================================================
__global__ __launch_bounds__(256) void k_hpack() {
    __shared__ float sc[32];
    __shared__ float qsum[8][32];
    __shared__ int degCnt;
    __shared__ int degList[32];
    const int t = threadIdx.x;
    const int cb = blockIdx.x;          // half-blob index 0..127
    const int b = blockIdx.y;
    const int j0 = cb * 32;             // 32 j columns per CTA

    if (t == 0) degCnt = 0;
    {
        const int jl = t & 31;
        const int sl = t >> 5;          // slice 0..7 of 16 partials each
        float cs = 0.f;
        #pragma unroll
        for (int s = 0; s < ISPLIT / 8; ++s)
            cs += g_part[sl * (ISPLIT / 8) + s][b * Nn + j0 + jl];
        qsum[sl][jl] = cs;
    }
    __syncthreads();
    if (t < 32) {
        float cs = 0.f;
        #pragma unroll
        for (int s = 0; s < 8; ++s) cs += qsum[s][t];
        sc[t] = cs > 0.f ? (SCALE_HS / cs) : (SCALE_HS / (float)Nn);
        if (!(cs > 0.f)) {
            const int k = atomicAdd(&degCnt, 1);
            degList[k] = t;
        }
    }
    __syncthreads();

    // Patch degenerate columns of p (normally degCnt == 0)
    for (int l = 0; l < degCnt; ++l) {
        const int j = j0 + degList[l];
        for (int i = t; i < Nn; i += 256)
            g_p[((size_t)(b * Nn) + i) * Nn + j] = __ushort_as_half(0x3C00);
    }

    // Pack this half-blob: 2048 halfs. Blob index = b*128 + cb.
    __half* __restrict__ dst = g_hsH + (size_t)(b * 128 + cb) * 2560;
    #pragma unroll
    for (int r = 0; r < 8; ++r) {
        const int o = t + r * 256;              // 0..2047
        const int seg = o >> 5, pos = o & 31;
        const int ks2 = seg >> 5, lane = seg & 31;
        const int lq = lane >> 2, lm = lane & 3;
        const int nt = pos >> 2, q = pos & 3;
        const int jl = ks2 * 16 + 2 * lm + (q & 1) + (q >> 1) * 8;   // 0..31
        const int f  = nt * 8 + lq;
        const float v = g_h[((size_t)(b * Nn) + j0 + jl) * 64 + f] * sc[jl];
        dst[seg * 40 + pos] = __float2half_rn(v);
    }
}

// ============================================================================
// Kernel 4 (hot): pure fp16 GEMM out' = P @ hs' via mma.m16n8k16.
// A fragments via ldmatrix.x4; TI=64, 128 thr = 4 warps x 16 rows; 4-deep
// half pipeline. grid (64, Bc, 2) = 512 CTAs; smem 40KB. fp16 partial out.
// ============================================================================
__device__ __forceinline__ void issue_half(uint32_t stg,
                                           const __half* __restrict__ pB,
                                           const __half* __restrict__ hsHb,
                                           int hglob, int t) {
    // p tile: 64 rows x 64B data, dst row stride 80B (256 quads)
    const __half* __restrict__ psrc = pB + hglob * 32;
    #pragma unroll
    for (int q = 0; q < 2; ++q) {
        const int quad = t + q * 128;
        const int row = quad >> 2, c4 = quad & 3;
        CPA16(stg + (uint32_t)row * 80u + (uint32_t)c4 * 16u,
              psrc + (size_t)row * Nn + c4 * 8);
    }
    // hs blob: flat 5120B = 320 quads
    const __half* __restrict__ hsrc = hsHb + (size_t)hglob * 2560;
    const uint32_t hb = stg + ST_P;
    CPA16(hb + (uint32_t)t * 16u, hsrc + t * 8);
    CPA16(hb + (uint32_t)(t + 128) * 16u, hsrc + (t + 128) * 8);
    if (t < 64)
        CPA16(hb + (uint32_t)(t + 256) * 16u, hsrc + (t + 256) * 8);
}

__global__ __launch_bounds__(128, 5) void k_main() {
    extern __shared__ char dsm[];
    const uint32_t sm = smem_u32(dsm);

    const int t    = threadIdx.x;
    const int wid  = t >> 5;      // warp owns rows wid*16 .. wid*16+15
    const int lane = t & 31;
    const int lq   = lane >> 2;
    const int lm   = lane & 3;
    const int b    = blockIdx.y;
    const int i0   = blockIdx.x * TI;
    const int ks   = blockIdx.z;
    const int h0   = ks * NHC;

    const __half* __restrict__ pB   = g_p + ((size_t)(b * Nn + i0)) * Nn;
    const __half* __restrict__ hsHb = g_hsH + (size_t)b * 128 * 2560;

    // ldmatrix lane address pieces: tile = lane>>3 (0..3)
    //   row-in-warp-tile = (tile&1)*8 + (lane&7); k-half = tile>>1
    const uint32_t lmRow = (uint32_t)(wid * 16 + ((lane >> 3) & 1) * 8 + (lane & 7));
    const uint32_t lmOff = lmRow * 80u + (uint32_t)(lane >> 4) * 16u;

    float acc[8][4];
    #pragma unroll
    for (int nt = 0; nt < 8; ++nt)
        #pragma unroll
        for (int q = 0; q < 4; ++q) acc[nt][q] = 0.f;

    #pragma unroll
    for (int p = 0; p < 3; ++p) {
        issue_half(sm + (uint32_t)p * STAGE, pB, hsHb, h0 + p, t);
        asm volatile("cp.async.commit_group;" ::: "memory");
    }

    for (int h = 0; h < NHC; ++h) {
        asm volatile("cp.async.wait_group 2;" ::: "memory");
        __syncthreads();
        if (h + 3 < NHC)
            issue_half(sm + (uint32_t)((h + 3) & 3) * STAGE, pB, hsHb,
                       h0 + h + 3, t);
        asm volatile("cp.async.commit_group;" ::: "memory");

        const uint32_t stg = sm + (uint32_t)(h & 3) * STAGE;
        const uint32_t hsb = stg + ST_P;

        #pragma unroll
        for (int ks2 = 0; ks2 < 2; ++ks2) {
            // B fragments: 4 x LDS.128 from seg (ks2*32 + lane)
            uint32_t bfr[16];
            #pragma unroll
            for (int v = 0; v < 4; ++v) {
                const uint32_t ba = hsb + (uint32_t)(ks2 * 32 + lane) * 80u
                                  + (uint32_t)v * 16u;
                asm volatile("ld.shared.v4.b32 {%0,%1,%2,%3}, [%4];"
                             : "=r"(bfr[v * 4]), "=r"(bfr[v * 4 + 1]),
                               "=r"(bfr[v * 4 + 2]), "=r"(bfr[v * 4 + 3])
                             : "r"(ba));
            }
            // A fragment: one ldmatrix.x4 (16 rows x 32B, conflict-free)
            uint32_t au[4];
            LDSM_X4(au[0], au[1], au[2], au[3],
                    stg + lmOff + (uint32_t)(ks2 * 32));
            #pragma unroll
            for (int nt = 0; nt < 8; ++nt) {
                const uint32_t b0 = bfr[(nt >> 1) * 4 + (nt & 1) * 2];
                const uint32_t b1 = bfr[(nt >> 1) * 4 + (nt & 1) * 2 + 1];
                MMA_F16(acc[nt], au, b0, b1);
            }
        }
    }

    // epilogue: undo SCALE_HS; store fp16 partials (half the write traffic)
    __half* __restrict__ pout = g_poutH[ks] + ((size_t)(b * Nn) + i0 + wid * 16) * 64;
    const float inv = 1.0f / SCALE_HS;
    #pragma unroll
    for (int nt = 0; nt < 8; ++nt) {
        const size_t base = (size_t)lq * 64 + nt * 8 + 2 * lm;
        *(uint32_t*)(pout + base) =
            packh2(acc[nt][0] * inv, acc[nt][1] * inv);
        *(uint32_t*)(pout + base + 8 * 64) =
            packh2(acc[nt][2] * inv, acc[nt][3] * inv);
    }
}

// ============================================================================
// Kernel 5: out = relu(p0 + p1)  (fp16 partials in, fp32 out)
// ============================================================================
__global__ __launch_bounds__(256) void k_fin(float* __restrict__ out) {
    const int idx = (blockIdx.x * 256 + threadIdx.x) * 8;
    const uint4 a = *(const uint4*)(&g_poutH[0][idx]);
    const uint4 c = *(const uint4*)(&g_poutH[1][idx]);
    float4 r0, r1;
    {
        const float2 a0 = h2f2(a.x), c0 = h2f2(c.x);
        const float2 a1 = h2f2(a.y), c1 = h2f2(c.y);
        r0.x = fmaxf(a0.x + c0.x, 0.f);
        r0.y = fmaxf(a0.y + c0.y, 0.f);
        r0.z = fmaxf(a1.x + c1.x, 0.f);
        r0.w = fmaxf(a1.y + c1.y, 0.f);
    }
    {
        const float2 a2 = h2f2(a.z), c2 = h2f2(c.z);
        const float2 a3 = h2f2(a.w), c3 = h2f2(c.w);
        r1.x = fmaxf(a2.x + c2.x, 0.f);
        r1.y = fmaxf(a2.y + c2.y, 0.f);
        r1.z = fmaxf(a3.x + c3.x, 0.f);
        r1.w = fmaxf(a3.y + c3.y, 0.f);
    }
    *(float4*)(out + idx)     = r0;
    *(float4*)(out + idx + 4) = r1;
}

// ============================================================================
extern "C" void kernel_launch(void* const* d_in, const int* in_sizes, int n_in,
                              void* d_out, int out_size) {
    const float *inp = nullptr, *adj = nullptr, *W = nullptr, *a = nullptr;
    for (int i = 0; i < n_in; ++i) {
        switch (in_sizes[i]) {
            case 1048576:  inp = (const float*)d_in[i]; break; // 4*4096*64
            case 67108864: adj = (const float*)d_in[i]; break; // 4*4096*4096
            case 4096:     W   = (const float*)d_in[i]; break; // 64*64
            case 128:      a   = (const float*)d_in[i]; break; // 128*1
            default: break;
        }
    }
    float* out = (float*)d_out;

    cudaFuncSetAttribute(k_main, cudaFuncAttributeMaxDynamicSharedMemorySize,
                         SM_TOTAL);

    k_prep<<<Bc * Nn / 4, 256>>>(inp, W, a);

    dim3 g2(Nn / 2048, ISPLIT, Bc);
    k_expsum<<<g2, 256>>>(adj);

    dim3 g3(128, Bc);
    k_hpack<<<g3, 256>>>();

    dim3 g4(Nn / TI, Bc, KSPLIT);
    k_main<<<g4, 128, SM_TOTAL>>>();

    k_fin<<<Bc * Nn * Ff / 2048, 256>>>(out);
}